// round 7
// baseline (speedup 1.0000x reference)
#include <cuda_runtime.h>
#include <math.h>

#define NTHR 512
#define NC 8            // cluster size (portable max -> guaranteed schedulable)

#define NB 2
#define NF 32
#define ND 512
#define NH 8
#define NHD 64
#define NFF 2048
#define NL 4
#define NM 256

// ---------------- persistent device state (no allocs) ----------------
__device__ __align__(16) float g_K [NL][NB][NF][ND];
__device__ __align__(16) float g_V [NL][NB][NF][ND];
__device__ __align__(16) float g_Vt[NL][NB][NF][ND];
__device__ __align__(16) float g_CA[NL][NB][NF][ND];
__device__ __align__(16) float g_gb[NL * 3][NB][2 * ND];
__device__ __align__(16) float g_ppe[NF][ND];
__device__ __align__(16) float g_x0[NB][ND];
__device__ __align__(16) float g_q [NB][ND];
__device__ __align__(16) float g_y1[NB][ND];
__device__ __align__(16) float g_x2[NB][ND];
__device__ __align__(16) float g_h [NB][NFF];
__device__ __align__(16) float g_y3[NB][ND];

struct __align__(16) Smem {
    float x[1024];      // generic dual-batch vector
    float h[4096];      // FF hidden dual-batch / 8-row x for precompute GEMM
    float part[4096];   // GEMV reduction scratch (16 KB)
    float o[1024];      // attention output dual-batch
    float att[512];     // softmax weights [b][h][j]
    float red[64];      // SALN reduction scratch
};

// ---------------- HW cluster barrier (release/acquire + L1 inval) ----------
__device__ __forceinline__ void csync() {
    asm volatile("barrier.cluster.arrive.aligned;" ::: "memory");
    asm volatile("barrier.cluster.wait.aligned;" ::: "memory");
}

// ---------------- redundant dual-batch SALN over arr (1024) ---------------
// threads 0..255 handle batch0, 256..511 batch1. G = [gamma512|beta512].
__device__ __forceinline__ void saln512(float* arr, const float* G0, const float* G1,
                                        const float* add0, const float* add1,
                                        float* red) {
    int tid = threadIdx.x;
    int half = tid >> 8, t = tid & 255;
    const float* G = half ? G1 : G0;
    const float* ad = half ? add1 : add0;
    float a0 = arr[half * 512 + t], a1 = arr[half * 512 + t + 256];
    float s = a0 + a1, q = a0 * a0 + a1 * a1;
#pragma unroll
    for (int o = 16; o; o >>= 1) {
        s += __shfl_xor_sync(0xffffffffu, s, o);
        q += __shfl_xor_sync(0xffffffffu, q, o);
    }
    int wid = tid >> 5;
    if ((tid & 31) == 0) { red[wid] = s; red[16 + wid] = q; }
    __syncthreads();
    if (tid < 2) {
        float S = 0.f, Q = 0.f;
#pragma unroll
        for (int k = 0; k < 8; k++) { S += red[tid * 8 + k]; Q += red[16 + tid * 8 + k]; }
        float mu = S * (1.f / 512.f);
        red[32 + tid] = mu;
        red[34 + tid] = rsqrtf(Q * (1.f / 512.f) - mu * mu + 1e-5f);
    }
    __syncthreads();
    float mu = red[32 + half], rs = red[34 + half];
    float o0 = (a0 - mu) * rs * G[t] + G[512 + t];
    float o1 = (a1 - mu) * rs * G[t + 256] + G[512 + t + 256];
    if (ad) { o0 += ad[t]; o1 += ad[t + 256]; }
    __syncthreads();
    arr[half * 512 + t] = o0; arr[half * 512 + t + 256] = o1;
    __syncthreads();
}

// ---- 32-col dual-batch GEMV tile, float4 weight loads, 512 threads --------
// W pre-offset to (row0, colbase). Valid outputs for threadIdx.x < 32.
template <int K>
__device__ __forceinline__ void dgemv32(const float* __restrict__ W, int ldw,
                                        const float* __restrict__ x0,
                                        const float* __restrict__ x1,
                                        float* __restrict__ part,
                                        float& o0, float& o1) {
    const int G = 64, KE = K / G;
    int tq = threadIdx.x & 7, te = threadIdx.x >> 3;       // te: 0..63
    const float* Wt = W + (size_t)(te * KE) * ldw + tq * 4;
    float a0 = 0.f, a1 = 0.f, a2 = 0.f, a3 = 0.f;
    float b0 = 0.f, b1 = 0.f, b2 = 0.f, b3 = 0.f;
#pragma unroll 8
    for (int e = 0; e < KE; e++) {
        float4 w = *reinterpret_cast<const float4*>(Wt + (size_t)e * ldw);
        float xa = x0[te * KE + e], xb = x1[te * KE + e];
        a0 += xa * w.x; a1 += xa * w.y; a2 += xa * w.z; a3 += xa * w.w;
        b0 += xb * w.x; b1 += xb * w.y; b2 += xb * w.z; b3 += xb * w.w;
    }
    __syncthreads();                    // protect part reuse
    float* P = part + te * 64 + tq * 4;
    P[0] = a0; P[1] = a1; P[2] = a2; P[3] = a3;
    P[32] = b0; P[33] = b1; P[34] = b2; P[35] = b3;
    __syncthreads();
    o0 = 0.f; o1 = 0.f;
    if (threadIdx.x < 32) {
        float s0 = 0.f, s1 = 0.f;
#pragma unroll
        for (int g = 0; g < 64; g++) {
            s0 += part[g * 64 + threadIdx.x];
            s1 += part[g * 64 + 32 + threadIdx.x];
        }
        o0 = s0; o1 = s1;
    }
}

// ---- 8-row x 64-col GEMM tile, K=512, scalar coalesced (precompute only) --
// returns result for row = tid>>6, col = colbase + (tid&63). W pre-offset.
__device__ __forceinline__ float gemm8x64_512(const float* __restrict__ W, int ldw,
                                              const float* __restrict__ xs,
                                              float* __restrict__ part) {
    int col = threadIdx.x & 63, kg = threadIdx.x >> 6;     // 8 k-groups
    const float* Wp = W + (size_t)(kg * 64) * ldw + col;
    float acc[8];
#pragma unroll
    for (int rr = 0; rr < 8; rr++) acc[rr] = 0.f;
#pragma unroll 8
    for (int e = 0; e < 64; e++) {
        float w = Wp[(size_t)e * ldw];
#pragma unroll
        for (int rr = 0; rr < 8; rr++) acc[rr] += xs[rr * 512 + kg * 64 + e] * w;
    }
    __syncthreads();
#pragma unroll
    for (int rr = 0; rr < 8; rr++) part[(kg * 8 + rr) * 64 + col] = acc[rr];
    __syncthreads();
    int orr = threadIdx.x >> 6, ocol = threadIdx.x & 63;
    float s = 0.f;
#pragma unroll
    for (int k = 0; k < 8; k++) s += part[(k * 8 + orr) * 64 + ocol];
    return s;
}

// ---------------------------------------------------------------------------
__global__ void __launch_bounds__(NTHR) __cluster_dims__(NC, 1, 1) mega(
    const float* __restrict__ content, const float* __restrict__ style,
    const float* __restrict__ init_st,
    const float* __restrict__ motion_W, const float* __restrict__ motion_b,
    const float* __restrict__ motionr_W, const float* __restrict__ motionr_b,
    const float* __restrict__ sa_Wq, const float* __restrict__ sa_bq,
    const float* __restrict__ sa_Wk, const float* __restrict__ sa_bk,
    const float* __restrict__ sa_Wv, const float* __restrict__ sa_bv,
    const float* __restrict__ sa_Wo, const float* __restrict__ sa_bo,
    const float* __restrict__ ca_Wv, const float* __restrict__ ca_bv,
    const float* __restrict__ ca_Wo, const float* __restrict__ ca_bo,
    const float* __restrict__ ff_W1, const float* __restrict__ ff_b1,
    const float* __restrict__ ff_W2, const float* __restrict__ ff_b2,
    const float* __restrict__ saln_W, const float* __restrict__ saln_b,
    float* __restrict__ outp)
{
    __shared__ Smem sm;
    const int cta = blockIdx.x, tid = threadIdx.x;

    // ================= P0: PPE + SALN gamma/beta + Vt = content@Wv+bv =======
    for (int idx = cta * NTHR + tid; idx < NF * ND; idx += NC * NTHR) {
        int f = idx >> 9, d = idx & 511;
        float divv = expf((float)(d & ~1) * (-9.210340371976184f / 512.0f));
        float a = (float)(f % 30) * divv;
        g_ppe[f][d] = (d & 1) ? cosf(a) : sinf(a);
    }
    for (int u = tid; u < 1024; u += NTHR) sm.x[u] = style[u];
    __syncthreads();
    for (int t = cta; t < 384; t += NC) {         // 12 ls * 32 coltiles of 32
        int ls = t >> 5, colbase = (t & 31) * 32;
        float o0, o1;
        dgemv32<512>(saln_W + (size_t)ls * 524288 + colbase, 1024,
                     sm.x, sm.x + 512, sm.part, o0, o1);
        if (tid < 32) {
            int col = colbase + tid;
            float bb = saln_b[ls * 1024 + col];
            g_gb[ls][0][col] = o0 + bb;
            g_gb[ls][1][col] = o1 + bb;
        }
    }
    for (int t = cta; t < 256; t += NC) {         // 4l * 8 coltiles(64) * 8 rowgrps
        int l = t >> 6, ct = (t >> 3) & 7, rg = t & 7;
        int colbase = ct * 64;
        __syncthreads();
        for (int u = tid; u < 4096; u += NTHR) sm.h[u] = content[(size_t)rg * 4096 + u];
        __syncthreads();
        float s = gemm8x64_512(ca_Wv + (size_t)l * 262144 + colbase, 512, sm.h, sm.part);
        int row = rg * 8 + (tid >> 6);
        int col = colbase + (tid & 63);
        g_Vt[l][row >> 5][row & 31][col] = s + ca_bv[l * 512 + col];
    }
    csync();

    // ================= P1: CA = Vt@Wo+bo, emb0 ===============================
    for (int t = cta; t < 256; t += NC) {
        int l = t >> 6, ct = (t >> 3) & 7, rg = t & 7;
        int colbase = ct * 64;
        __syncthreads();
        const float* vt = &g_Vt[l][0][0][0];
        for (int u = tid; u < 4096; u += NTHR) sm.h[u] = vt[(size_t)rg * 4096 + u];
        __syncthreads();
        float s = gemm8x64_512(ca_Wo + (size_t)l * 262144 + colbase, 512, sm.h, sm.part);
        int row = rg * 8 + (tid >> 6);
        int col = colbase + (tid & 63);
        g_CA[l][row >> 5][row & 31][col] = s + ca_bo[l * 512 + col];
    }
    __syncthreads();
    if (tid < 256) { sm.x[tid] = init_st[tid]; sm.x[512 + tid] = init_st[256 + tid]; }
    __syncthreads();
    for (int t = cta; t < 16; t += NC) {          // emb0: 512 cols, K=256
        int colbase = t * 32;
        float o0, o1;
        dgemv32<256>(motion_W + colbase, 512, sm.x, sm.x + 512, sm.part, o0, o1);
        if (tid < 32) {
            int col = colbase + tid;
            float ex = motion_b[col] + g_ppe[0][col];
            g_x0[0][col] = o0 + ex;
            g_x0[1][col] = o1 + ex;
        }
    }
    csync();

    // ================= autoregressive decode =================================
    for (int i = 0; i < NF; i++) {
        for (int l = 0; l < NL; l++) {
            // ---- A: (redundant saln3 of prev layer) + q/k/v tiles ----
            if (l == 0) {
                for (int u = tid; u < 1024; u += NTHR) sm.x[u] = ((const float*)g_x0)[u];
                __syncthreads();
            } else {
                for (int u = tid; u < 1024; u += NTHR) sm.x[u] = ((const float*)g_y3)[u];
                __syncthreads();
                saln512(sm.x, g_gb[(l - 1) * 3 + 2][0], g_gb[(l - 1) * 3 + 2][1],
                        0, 0, sm.red);
                if (cta == 0) {
                    ((float*)g_x0)[tid] = sm.x[tid];
                    ((float*)g_x0)[tid + 512] = sm.x[tid + 512];
                }
            }
            for (int t = cta; t < 48; t += NC) {
                int which = t >> 4, ct = t & 15;
                const float* W = (which == 0 ? sa_Wq : which == 1 ? sa_Wk : sa_Wv)
                               + (size_t)l * 262144 + ct * 32;
                float o0, o1;
                dgemv32<512>(W, 512, sm.x, sm.x + 512, sm.part, o0, o1);
                if (tid < 32) {
                    int col = ct * 32 + tid;
                    const float* bias = which == 0 ? sa_bq : which == 1 ? sa_bk : sa_bv;
                    float bb = bias[l * 512 + col];
                    o0 += bb; o1 += bb;
                    if (which == 0)      { g_q[0][col] = o0;       g_q[1][col] = o1; }
                    else if (which == 1) { g_K[l][0][i][col] = o0; g_K[l][1][i][col] = o1; }
                    else                 { g_V[l][0][i][col] = o0; g_V[l][1][i][col] = o1; }
                }
            }
            csync();

            // ---- B: redundant scores+softmax+attn-sum, then y1 tiles ----
            {
                for (int u = tid; u < 1024; u += NTHR) sm.x[u] = ((const float*)g_q)[u];
                __syncthreads();
                int wid = tid >> 5, lane = tid & 31;
                int b = wid >> 3, h = wid & 7;
                float sc = -1e30f;
                if (lane <= i) {
                    const float4* kp = reinterpret_cast<const float4*>(&g_K[l][b][lane][h * 64]);
                    const float4* qp = reinterpret_cast<const float4*>(&sm.x[b * 512 + h * 64]);
                    float d = 0.f;
#pragma unroll
                    for (int e = 0; e < 16; e++) {
                        float4 kk = kp[e], qq = qp[e];
                        d += qq.x * kk.x + qq.y * kk.y + qq.z * kk.z + qq.w * kk.w;
                    }
                    sc = d * 0.125f - exp2f(-(float)(h + 1)) * (float)((i - lane) / 30);
                }
                float mx = sc;
#pragma unroll
                for (int o = 16; o; o >>= 1) mx = fmaxf(mx, __shfl_xor_sync(0xffffffffu, mx, o));
                float ev = (lane <= i) ? expf(sc - mx) : 0.f;
                float smm = ev;
#pragma unroll
                for (int o = 16; o; o >>= 1) smm += __shfl_xor_sync(0xffffffffu, smm, o);
                sm.att[b * 256 + h * 32 + lane] = ev / smm;
                __syncthreads();
                if (tid < 256) {                  // o = att @ V (float4 lanes)
                    int bb = tid >> 7, quad = tid & 127;
                    int hh = quad >> 4;
                    float4 acc = make_float4(0.f, 0.f, 0.f, 0.f);
                    for (int j = 0; j <= i; j++) {
                        float a = sm.att[bb * 256 + hh * 32 + j];
                        float4 v = reinterpret_cast<const float4*>(&g_V[l][bb][j][0])[quad];
                        acc.x += a * v.x; acc.y += a * v.y;
                        acc.z += a * v.z; acc.w += a * v.w;
                    }
                    reinterpret_cast<float4*>(sm.o)[bb * 128 + quad] = acc;
                }
                __syncthreads();
                for (int t = cta; t < 16; t += NC) {   // y1 = o@Wo + bo + x0
                    int colbase = t * 32;
                    float o0, o1;
                    dgemv32<512>(sa_Wo + (size_t)l * 262144 + colbase, 512,
                                 sm.o, sm.o + 512, sm.part, o0, o1);
                    if (tid < 32) {
                        int col = colbase + tid;
                        float bb2 = sa_bo[l * 512 + col];
                        g_y1[0][col] = o0 + bb2 + g_x0[0][col];
                        g_y1[1][col] = o1 + bb2 + g_x0[1][col];
                    }
                }
            }
            csync();

            // ---- C: redundant saln1+CA+saln2, then FF1 tiles ----
            {
                for (int u = tid; u < 1024; u += NTHR) sm.x[u] = ((const float*)g_y1)[u];
                __syncthreads();
                saln512(sm.x, g_gb[l * 3 + 0][0], g_gb[l * 3 + 0][1],
                        &g_CA[l][0][i][0], &g_CA[l][1][i][0], sm.red);
                saln512(sm.x, g_gb[l * 3 + 1][0], g_gb[l * 3 + 1][1], 0, 0, sm.red);
                if (cta == 0) {
                    ((float*)g_x2)[tid] = sm.x[tid];
                    ((float*)g_x2)[tid + 512] = sm.x[tid + 512];
                }
                for (int t = cta; t < 64; t += NC) {
                    int colbase = t * 32;
                    float o0, o1;
                    dgemv32<512>(ff_W1 + (size_t)l * 1048576 + colbase, 2048,
                                 sm.x, sm.x + 512, sm.part, o0, o1);
                    if (tid < 32) {
                        int col = colbase + tid;
                        float bb = ff_b1[l * 2048 + col];
                        g_h[0][col] = fmaxf(o0 + bb, 0.f);
                        g_h[1][col] = fmaxf(o1 + bb, 0.f);
                    }
                }
            }
            csync();

            // ---- D: FF2 tiles -> y3 ----
            {
                for (int u = tid; u < 1024; u += NTHR)
                    reinterpret_cast<float4*>(sm.h)[u] =
                        reinterpret_cast<const float4*>(&g_h[0][0])[u];
                __syncthreads();
                for (int t = cta; t < 16; t += NC) {
                    int colbase = t * 32;
                    float o0, o1;
                    dgemv32<2048>(ff_W2 + (size_t)l * 1048576 + colbase, 512,
                                  sm.h, sm.h + 2048, sm.part, o0, o1);
                    if (tid < 32) {
                        int col = colbase + tid;
                        float bb = ff_b2[l * 512 + col];
                        g_y3[0][col] = o0 + bb + g_x2[0][col];
                        g_y3[1][col] = o1 + bb + g_x2[1][col];
                    }
                }
            }
            csync();
        } // layers

        // ---- OUT: row i = saln3(y3) @ motionr_W + br ----
        {
            for (int u = tid; u < 1024; u += NTHR) sm.x[u] = ((const float*)g_y3)[u];
            __syncthreads();
            saln512(sm.x, g_gb[11][0], g_gb[11][1], 0, 0, sm.red);
            for (int t = cta; t < 8; t += NC) {
                int colbase = t * 32;
                float o0, o1;
                dgemv32<512>(motionr_W + colbase, 256, sm.x, sm.x + 512, sm.part, o0, o1);
                if (tid < 32) {
                    int col = colbase + tid;
                    float bb = motionr_b[col];
                    outp[(size_t)i * 256 + col] = o0 + bb;
                    outp[8192 + (size_t)i * 256 + col] = o1 + bb;
                }
            }
        }
        csync();

        // ---- EMB: x0 = out_row @ motion_W + bm + ppe[i+1] ----
        if (i < NF - 1) {
            if (tid < 256) {
                sm.x[tid] = outp[(size_t)i * 256 + tid];
                sm.x[512 + tid] = outp[8192 + (size_t)i * 256 + tid];
            }
            __syncthreads();
            for (int t = cta; t < 16; t += NC) {
                int colbase = t * 32;
                float o0, o1;
                dgemv32<256>(motion_W + colbase, 512, sm.x, sm.x + 512, sm.part, o0, o1);
                if (tid < 32) {
                    int col = colbase + tid;
                    float ex = motion_b[col] + g_ppe[i + 1][col];
                    g_x0[0][col] = o0 + ex;
                    g_x0[1][col] = o1 + ex;
                }
            }
            csync();
        }
    } // steps
}

// ---------------------------------------------------------------------------
extern "C" void kernel_launch(void* const* d_in, const int* in_sizes, int n_in,
                              void* d_out, int out_size) {
    mega<<<NC, NTHR>>>(
        (const float*)d_in[0],  (const float*)d_in[1],  (const float*)d_in[2],
        (const float*)d_in[3],  (const float*)d_in[4],  (const float*)d_in[5],
        (const float*)d_in[6],
        (const float*)d_in[7],  (const float*)d_in[8],  (const float*)d_in[9],
        (const float*)d_in[10], (const float*)d_in[11], (const float*)d_in[12],
        (const float*)d_in[13], (const float*)d_in[14],
        /* ca_Wq/bq/Wk/bk (15-18) unused: one-hot cross-attn softmax */
        (const float*)d_in[19], (const float*)d_in[20], (const float*)d_in[21],
        (const float*)d_in[22],
        (const float*)d_in[23], (const float*)d_in[24], (const float*)d_in[25],
        (const float*)d_in[26],
        (const float*)d_in[27], (const float*)d_in[28],
        (float*)d_out);
    (void)in_sizes; (void)n_in; (void)out_size;
}

// round 8
// speedup vs baseline: 1.5418x; 1.5418x over previous
#include <cuda_runtime.h>
#include <cuda_fp16.h>
#include <math.h>

#define NTHR 512
#define NC 8            // cluster size (portable max -> guaranteed schedulable)

#define NB 2
#define NF 32
#define ND 512
#define NH 8
#define NHD 64
#define NFF 2048
#define NL 4
#define NM 256

// ---------------- persistent device state (no allocs) ----------------
__device__ __align__(16) float g_K [NL][NB][NF][ND];
__device__ __align__(16) float g_V [NL][NB][NF][ND];
__device__ __align__(16) float g_Vt[NL][NB][NF][ND];
__device__ __align__(16) float g_CA[NL][NB][NF][ND];
__device__ __align__(16) float g_gb[NL * 3][NB][2 * ND];
__device__ __align__(16) float g_ppe[NF][ND];
__device__ __align__(16) float g_x0[NB][ND];
__device__ __align__(16) float g_q [NB][ND];
__device__ __align__(16) float g_y1[NB][ND];
__device__ __align__(16) float g_x2[NB][ND];
__device__ __align__(16) float g_h [NB][NFF];
__device__ __align__(16) float g_y3[NB][ND];

// fp16 weight copies (converted in preamble; halves step-loop traffic)
__device__ __align__(16) __half hWq[NL * ND * ND];
__device__ __align__(16) __half hWk[NL * ND * ND];
__device__ __align__(16) __half hWv[NL * ND * ND];
__device__ __align__(16) __half hWo[NL * ND * ND];
__device__ __align__(16) __half hW1[NL * ND * NFF];
__device__ __align__(16) __half hW2[NL * NFF * ND];
__device__ __align__(16) __half hMo[NM * ND];
__device__ __align__(16) __half hMr[ND * NM];

struct __align__(16) Smem {
    float x[1024];      // generic dual-batch vector
    float h[4096];      // FF hidden dual-batch / 8-row x for precompute GEMM
    float part[4096];   // GEMV reduction scratch
    float o[1024];      // attention output dual-batch
    float att[512];     // softmax weights [b][h][j]
    float red[64];      // SALN reduction scratch
};

// ---------------- HW cluster barrier ----------------
__device__ __forceinline__ void csync() {
    asm volatile("barrier.cluster.arrive.aligned;" ::: "memory");
    asm volatile("barrier.cluster.wait.aligned;" ::: "memory");
}

// ---------------- fp32 -> fp16 strided converter ----------------
__device__ __forceinline__ void cvt_half(__half* dst, const float* __restrict__ src,
                                         int n2, int gtid, int gstride) {
    const float2* s = reinterpret_cast<const float2*>(src);
    __half2* d = reinterpret_cast<__half2*>(dst);
    for (int i = gtid; i < n2; i += gstride)
        d[i] = __floats2half2_rn(s[i].x, s[i].y);
}

// ---------------- redundant dual-batch SALN over arr (1024) ---------------
__device__ __forceinline__ void saln512(float* arr, const float* G0, const float* G1,
                                        const float* add0, const float* add1,
                                        float* red) {
    int tid = threadIdx.x;
    int half = tid >> 8, t = tid & 255;
    const float* G = half ? G1 : G0;
    const float* ad = half ? add1 : add0;
    float a0 = arr[half * 512 + t], a1 = arr[half * 512 + t + 256];
    float s = a0 + a1, q = a0 * a0 + a1 * a1;
#pragma unroll
    for (int o = 16; o; o >>= 1) {
        s += __shfl_xor_sync(0xffffffffu, s, o);
        q += __shfl_xor_sync(0xffffffffu, q, o);
    }
    int wid = tid >> 5;
    if ((tid & 31) == 0) { red[wid] = s; red[16 + wid] = q; }
    __syncthreads();
    if (tid < 2) {
        float S = 0.f, Q = 0.f;
#pragma unroll
        for (int k = 0; k < 8; k++) { S += red[tid * 8 + k]; Q += red[16 + tid * 8 + k]; }
        float mu = S * (1.f / 512.f);
        red[32 + tid] = mu;
        red[34 + tid] = rsqrtf(Q * (1.f / 512.f) - mu * mu + 1e-5f);
    }
    __syncthreads();
    float mu = red[32 + half], rs = red[34 + half];
    float o0 = (a0 - mu) * rs * G[t] + G[512 + t];
    float o1 = (a1 - mu) * rs * G[t + 256] + G[512 + t + 256];
    if (ad) { o0 += ad[t]; o1 += ad[t + 256]; }
    __syncthreads();
    arr[half * 512 + t] = o0; arr[half * 512 + t + 256] = o1;
    __syncthreads();
}

// ---- fp16-weight dual-batch GEMV tile: COLS cols in ONE load wave ---------
// W pre-offset to (row0, colbase), ldw in halves. Outputs valid for tid<COLS.
template <int COLS, int K>
__device__ __forceinline__ void dgemvh(const __half* __restrict__ W, int ldw,
                                       const float* __restrict__ x0,
                                       const float* __restrict__ x1,
                                       float* __restrict__ part,
                                       float& o0, float& o1) {
    const int QP = COLS / 8;            // 8-half quads per row
    const int G  = NTHR / QP;           // K-groups
    const int KE = K / G;
    int tid = threadIdx.x;
    int tq = tid % QP, te = tid / QP;
    const __half* Wt = W + (size_t)(te * KE) * ldw + tq * 8;
    float a[8] = {0,0,0,0,0,0,0,0}, b[8] = {0,0,0,0,0,0,0,0};
#pragma unroll
    for (int e = 0; e < KE; e++) {
        float4 w4 = *reinterpret_cast<const float4*>(Wt + (size_t)e * ldw);
        const __half2* hw = reinterpret_cast<const __half2*>(&w4);
        float xa = x0[te * KE + e], xb = x1[te * KE + e];
#pragma unroll
        for (int q = 0; q < 4; q++) {
            float2 f = __half22float2(hw[q]);
            a[2*q]   += xa * f.x; a[2*q+1] += xa * f.y;
            b[2*q]   += xb * f.x; b[2*q+1] += xb * f.y;
        }
    }
    // butterfly over te-values within each warp -> 16 effective groups
#pragma unroll
    for (int ofs = QP; ofs < 32; ofs <<= 1) {
#pragma unroll
        for (int c = 0; c < 8; c++) {
            a[c] += __shfl_xor_sync(0xffffffffu, a[c], ofs);
            b[c] += __shfl_xor_sync(0xffffffffu, b[c], ofs);
        }
    }
    __syncthreads();                    // protect part reuse
    int w = tid >> 5;
    if ((tid & 31) < QP) {
#pragma unroll
        for (int c = 0; c < 8; c++) {
            part[w * (2 * COLS) + tq * 8 + c] = a[c];
            part[w * (2 * COLS) + COLS + tq * 8 + c] = b[c];
        }
    }
    __syncthreads();
    o0 = 0.f; o1 = 0.f;
    if (tid < COLS) {
        float s0 = 0.f, s1 = 0.f;
#pragma unroll
        for (int k = 0; k < 16; k++) {
            s0 += part[k * (2 * COLS) + tid];
            s1 += part[k * (2 * COLS) + COLS + tid];
        }
        o0 = s0; o1 = s1;
    }
}

// ---- fp32 dual-batch 32-col GEMV (preamble only) --------------------------
template <int K>
__device__ __forceinline__ void dgemv32(const float* __restrict__ W, int ldw,
                                        const float* __restrict__ x0,
                                        const float* __restrict__ x1,
                                        float* __restrict__ part,
                                        float& o0, float& o1) {
    const int G = 64, KE = K / G;
    int tq = threadIdx.x & 7, te = threadIdx.x >> 3;
    const float* Wt = W + (size_t)(te * KE) * ldw + tq * 4;
    float a0 = 0.f, a1 = 0.f, a2 = 0.f, a3 = 0.f;
    float b0 = 0.f, b1 = 0.f, b2 = 0.f, b3 = 0.f;
#pragma unroll 8
    for (int e = 0; e < KE; e++) {
        float4 w = *reinterpret_cast<const float4*>(Wt + (size_t)e * ldw);
        float xa = x0[te * KE + e], xb = x1[te * KE + e];
        a0 += xa * w.x; a1 += xa * w.y; a2 += xa * w.z; a3 += xa * w.w;
        b0 += xb * w.x; b1 += xb * w.y; b2 += xb * w.z; b3 += xb * w.w;
    }
    __syncthreads();
    float* P = part + te * 64 + tq * 4;
    P[0] = a0; P[1] = a1; P[2] = a2; P[3] = a3;
    P[32] = b0; P[33] = b1; P[34] = b2; P[35] = b3;
    __syncthreads();
    o0 = 0.f; o1 = 0.f;
    if (threadIdx.x < 32) {
        float s0 = 0.f, s1 = 0.f;
#pragma unroll
        for (int g = 0; g < 64; g++) {
            s0 += part[g * 64 + threadIdx.x];
            s1 += part[g * 64 + 32 + threadIdx.x];
        }
        o0 = s0; o1 = s1;
    }
}

// ---- 8-row x 64-col GEMM tile, K=512 (preamble only) ----------------------
__device__ __forceinline__ float gemm8x64_512(const float* __restrict__ W, int ldw,
                                              const float* __restrict__ xs,
                                              float* __restrict__ part) {
    int col = threadIdx.x & 63, kg = threadIdx.x >> 6;
    const float* Wp = W + (size_t)(kg * 64) * ldw + col;
    float acc[8];
#pragma unroll
    for (int rr = 0; rr < 8; rr++) acc[rr] = 0.f;
#pragma unroll 8
    for (int e = 0; e < 64; e++) {
        float w = Wp[(size_t)e * ldw];
#pragma unroll
        for (int rr = 0; rr < 8; rr++) acc[rr] += xs[rr * 512 + kg * 64 + e] * w;
    }
    __syncthreads();
#pragma unroll
    for (int rr = 0; rr < 8; rr++) part[(kg * 8 + rr) * 64 + col] = acc[rr];
    __syncthreads();
    int orr = threadIdx.x >> 6, ocol = threadIdx.x & 63;
    float s = 0.f;
#pragma unroll
    for (int k = 0; k < 8; k++) s += part[(k * 8 + orr) * 64 + ocol];
    return s;
}

// ---------------------------------------------------------------------------
__global__ void __launch_bounds__(NTHR) __cluster_dims__(NC, 1, 1) mega(
    const float* __restrict__ content, const float* __restrict__ style,
    const float* __restrict__ init_st,
    const float* __restrict__ motion_W, const float* __restrict__ motion_b,
    const float* __restrict__ motionr_W, const float* __restrict__ motionr_b,
    const float* __restrict__ sa_Wq, const float* __restrict__ sa_bq,
    const float* __restrict__ sa_Wk, const float* __restrict__ sa_bk,
    const float* __restrict__ sa_Wv, const float* __restrict__ sa_bv,
    const float* __restrict__ sa_Wo, const float* __restrict__ sa_bo,
    const float* __restrict__ ca_Wv, const float* __restrict__ ca_bv,
    const float* __restrict__ ca_Wo, const float* __restrict__ ca_bo,
    const float* __restrict__ ff_W1, const float* __restrict__ ff_b1,
    const float* __restrict__ ff_W2, const float* __restrict__ ff_b2,
    const float* __restrict__ saln_W, const float* __restrict__ saln_b,
    float* __restrict__ outp)
{
    __shared__ Smem sm;
    const int cta = blockIdx.x, tid = threadIdx.x;
    const int gtid = cta * NTHR + tid, gstride = NC * NTHR;

    // ================= P0: weight conversion + PPE + gb + Vt ================
    cvt_half(hWq, sa_Wq, NL * ND * ND / 2, gtid, gstride);
    cvt_half(hWk, sa_Wk, NL * ND * ND / 2, gtid, gstride);
    cvt_half(hWv, sa_Wv, NL * ND * ND / 2, gtid, gstride);
    cvt_half(hWo, sa_Wo, NL * ND * ND / 2, gtid, gstride);
    cvt_half(hW1, ff_W1, NL * ND * NFF / 2, gtid, gstride);
    cvt_half(hW2, ff_W2, NL * NFF * ND / 2, gtid, gstride);
    cvt_half(hMo, motion_W, NM * ND / 2, gtid, gstride);
    cvt_half(hMr, motionr_W, ND * NM / 2, gtid, gstride);

    for (int idx = gtid; idx < NF * ND; idx += gstride) {
        int f = idx >> 9, d = idx & 511;
        float divv = expf((float)(d & ~1) * (-9.210340371976184f / 512.0f));
        float a = (float)(f % 30) * divv;
        g_ppe[f][d] = (d & 1) ? cosf(a) : sinf(a);
    }
    for (int u = tid; u < 1024; u += NTHR) sm.x[u] = style[u];
    __syncthreads();
    for (int t = cta; t < 384; t += NC) {         // 12 ls * 32 coltiles of 32
        int ls = t >> 5, colbase = (t & 31) * 32;
        float o0, o1;
        dgemv32<512>(saln_W + (size_t)ls * 524288 + colbase, 1024,
                     sm.x, sm.x + 512, sm.part, o0, o1);
        if (tid < 32) {
            int col = colbase + tid;
            float bb = saln_b[ls * 1024 + col];
            g_gb[ls][0][col] = o0 + bb;
            g_gb[ls][1][col] = o1 + bb;
        }
    }
    for (int t = cta; t < 256; t += NC) {         // Vt = content@Wv+bv
        int l = t >> 6, ct = (t >> 3) & 7, rg = t & 7;
        int colbase = ct * 64;
        __syncthreads();
        for (int u = tid; u < 4096; u += NTHR) sm.h[u] = content[(size_t)rg * 4096 + u];
        __syncthreads();
        float s = gemm8x64_512(ca_Wv + (size_t)l * 262144 + colbase, 512, sm.h, sm.part);
        int row = rg * 8 + (tid >> 6);
        int col = colbase + (tid & 63);
        g_Vt[l][row >> 5][row & 31][col] = s + ca_bv[l * 512 + col];
    }
    csync();

    // ================= P1: CA = Vt@Wo+bo, emb0 ===============================
    for (int t = cta; t < 256; t += NC) {
        int l = t >> 6, ct = (t >> 3) & 7, rg = t & 7;
        int colbase = ct * 64;
        __syncthreads();
        const float* vt = &g_Vt[l][0][0][0];
        for (int u = tid; u < 4096; u += NTHR) sm.h[u] = vt[(size_t)rg * 4096 + u];
        __syncthreads();
        float s = gemm8x64_512(ca_Wo + (size_t)l * 262144 + colbase, 512, sm.h, sm.part);
        int row = rg * 8 + (tid >> 6);
        int col = colbase + (tid & 63);
        g_CA[l][row >> 5][row & 31][col] = s + ca_bo[l * 512 + col];
    }
    __syncthreads();
    if (tid < 256) { sm.x[tid] = init_st[tid]; sm.x[512 + tid] = init_st[256 + tid]; }
    __syncthreads();
    for (int t = cta; t < 16; t += NC) {          // emb0 (fp32, once)
        int colbase = t * 32;
        float o0, o1;
        dgemv32<256>(motion_W + colbase, 512, sm.x, sm.x + 512, sm.part, o0, o1);
        if (tid < 32) {
            int col = colbase + tid;
            float ex = motion_b[col] + g_ppe[0][col];
            g_x0[0][col] = o0 + ex;
            g_x0[1][col] = o1 + ex;
        }
    }
    csync();

    // ================= autoregressive decode =================================
    for (int i = 0; i < NF; i++) {
        for (int l = 0; l < NL; l++) {
            // ---- A: (redundant saln3 of prev layer) + q/k/v (3 waves) ----
            if (l == 0) {
                for (int u = tid; u < 1024; u += NTHR) sm.x[u] = ((const float*)g_x0)[u];
                __syncthreads();
            } else {
                for (int u = tid; u < 1024; u += NTHR) sm.x[u] = ((const float*)g_y3)[u];
                __syncthreads();
                saln512(sm.x, g_gb[(l - 1) * 3 + 2][0], g_gb[(l - 1) * 3 + 2][1],
                        0, 0, sm.red);
                if (cta == 0) {
                    ((float*)g_x0)[tid] = sm.x[tid];
                    ((float*)g_x0)[tid + 512] = sm.x[tid + 512];
                }
            }
#pragma unroll
            for (int s = 0; s < 3; s++) {
                int t = cta * 3 + s;               // 24 tiles of 64 cols
                int m = t >> 3, ct = t & 7;
                const __half* W = (m == 0 ? hWq : m == 1 ? hWk : hWv)
                                + (size_t)l * 262144 + ct * 64;
                float o0, o1;
                dgemvh<64, 512>(W, 512, sm.x, sm.x + 512, sm.part, o0, o1);
                if (tid < 64) {
                    int col = ct * 64 + tid;
                    const float* bias = m == 0 ? sa_bq : m == 1 ? sa_bk : sa_bv;
                    float bb = bias[l * 512 + col];
                    o0 += bb; o1 += bb;
                    if (m == 0)      { g_q[0][col] = o0;       g_q[1][col] = o1; }
                    else if (m == 1) { g_K[l][0][i][col] = o0; g_K[l][1][i][col] = o1; }
                    else             { g_V[l][0][i][col] = o0; g_V[l][1][i][col] = o1; }
                }
            }
            csync();

            // ---- B: redundant scores+softmax+attn-sum, then y1 (1 wave) ----
            {
                for (int u = tid; u < 1024; u += NTHR) sm.x[u] = ((const float*)g_q)[u];
                __syncthreads();
                int wid = tid >> 5, lane = tid & 31;
                int b = wid >> 3, h = wid & 7;
                float sc = -1e30f;
                if (lane <= i) {
                    const float4* kp = reinterpret_cast<const float4*>(&g_K[l][b][lane][h * 64]);
                    const float4* qp = reinterpret_cast<const float4*>(&sm.x[b * 512 + h * 64]);
                    float d = 0.f;
#pragma unroll
                    for (int e = 0; e < 16; e++) {
                        float4 kk = kp[e], qq = qp[e];
                        d += qq.x * kk.x + qq.y * kk.y + qq.z * kk.z + qq.w * kk.w;
                    }
                    sc = d * 0.125f - exp2f(-(float)(h + 1)) * (float)((i - lane) / 30);
                }
                float mx = sc;
#pragma unroll
                for (int o = 16; o; o >>= 1) mx = fmaxf(mx, __shfl_xor_sync(0xffffffffu, mx, o));
                float ev = (lane <= i) ? expf(sc - mx) : 0.f;
                float smm = ev;
#pragma unroll
                for (int o = 16; o; o >>= 1) smm += __shfl_xor_sync(0xffffffffu, smm, o);
                sm.att[b * 256 + h * 32 + lane] = ev / smm;
                __syncthreads();
                if (tid < 256) {                  // o = att @ V
                    int bb = tid >> 7, quad = tid & 127;
                    int hh = quad >> 4;
                    float4 acc = make_float4(0.f, 0.f, 0.f, 0.f);
#pragma unroll 4
                    for (int j = 0; j <= i; j++) {
                        float a = sm.att[bb * 256 + hh * 32 + j];
                        float4 v = reinterpret_cast<const float4*>(&g_V[l][bb][j][0])[quad];
                        acc.x += a * v.x; acc.y += a * v.y;
                        acc.z += a * v.z; acc.w += a * v.w;
                    }
                    reinterpret_cast<float4*>(sm.o)[bb * 128 + quad] = acc;
                }
                __syncthreads();
                float o0, o1;
                dgemvh<64, 512>(hWo + (size_t)l * 262144 + cta * 64, 512,
                                sm.o, sm.o + 512, sm.part, o0, o1);
                if (tid < 64) {
                    int col = cta * 64 + tid;
                    float bb2 = sa_bo[l * 512 + col];
                    g_y1[0][col] = o0 + bb2 + g_x0[0][col];
                    g_y1[1][col] = o1 + bb2 + g_x0[1][col];
                }
            }
            csync();

            // ---- C: redundant saln1+CA+saln2, then FF1 (2 waves) ----
            {
                for (int u = tid; u < 1024; u += NTHR) sm.x[u] = ((const float*)g_y1)[u];
                __syncthreads();
                saln512(sm.x, g_gb[l * 3 + 0][0], g_gb[l * 3 + 0][1],
                        &g_CA[l][0][i][0], &g_CA[l][1][i][0], sm.red);
                saln512(sm.x, g_gb[l * 3 + 1][0], g_gb[l * 3 + 1][1], 0, 0, sm.red);
                if (cta == 0) {
                    ((float*)g_x2)[tid] = sm.x[tid];
                    ((float*)g_x2)[tid + 512] = sm.x[tid + 512];
                }
#pragma unroll
                for (int s = 0; s < 2; s++) {
                    int colbase = (cta * 2 + s) * 128;     // 16 tiles of 128
                    float o0, o1;
                    dgemvh<128, 512>(hW1 + (size_t)l * 1048576 + colbase, 2048,
                                     sm.x, sm.x + 512, sm.part, o0, o1);
                    if (tid < 128) {
                        int col = colbase + tid;
                        float bb = ff_b1[l * 2048 + col];
                        g_h[0][col] = fmaxf(o0 + bb, 0.f);
                        g_h[1][col] = fmaxf(o1 + bb, 0.f);
                    }
                }
            }
            csync();

            // ---- D: FF2 (1 wave) -> y3 ----
            {
                for (int u = tid; u < 1024; u += NTHR)
                    reinterpret_cast<float4*>(sm.h)[u] =
                        reinterpret_cast<const float4*>(&g_h[0][0])[u];
                __syncthreads();
                float o0, o1;
                dgemvh<64, 2048>(hW2 + (size_t)l * 1048576 + cta * 64, 512,
                                 sm.h, sm.h + 2048, sm.part, o0, o1);
                if (tid < 64) {
                    int col = cta * 64 + tid;
                    float bb = ff_b2[l * 512 + col];
                    g_y3[0][col] = o0 + bb + g_x2[0][col];
                    g_y3[1][col] = o1 + bb + g_x2[1][col];
                }
            }
            csync();
        } // layers

        // ---- OUT: row i = saln3(y3) @ motionr_W + br (1 wave) ----
        {
            for (int u = tid; u < 1024; u += NTHR) sm.x[u] = ((const float*)g_y3)[u];
            __syncthreads();
            saln512(sm.x, g_gb[11][0], g_gb[11][1], 0, 0, sm.red);
            float o0, o1;
            dgemvh<32, 512>(hMr + cta * 32, 256, sm.x, sm.x + 512, sm.part, o0, o1);
            if (tid < 32) {
                int col = cta * 32 + tid;
                float bb = motionr_b[col];
                outp[(size_t)i * 256 + col] = o0 + bb;
                outp[8192 + (size_t)i * 256 + col] = o1 + bb;
            }
        }
        csync();

        // ---- EMB: x0 = out_row @ motion_W + bm + ppe[i+1] (1 wave) ----
        if (i < NF - 1) {
            if (tid < 256) {
                sm.x[tid] = outp[(size_t)i * 256 + tid];
                sm.x[512 + tid] = outp[8192 + (size_t)i * 256 + tid];
            }
            __syncthreads();
            float o0, o1;
            dgemvh<64, 256>(hMo + cta * 64, 512, sm.x, sm.x + 512, sm.part, o0, o1);
            if (tid < 64) {
                int col = cta * 64 + tid;
                float ex = motion_b[col] + g_ppe[i + 1][col];
                g_x0[0][col] = o0 + ex;
                g_x0[1][col] = o1 + ex;
            }
            csync();
        }
    } // steps
}

// ---------------------------------------------------------------------------
extern "C" void kernel_launch(void* const* d_in, const int* in_sizes, int n_in,
                              void* d_out, int out_size) {
    mega<<<NC, NTHR>>>(
        (const float*)d_in[0],  (const float*)d_in[1],  (const float*)d_in[2],
        (const float*)d_in[3],  (const float*)d_in[4],  (const float*)d_in[5],
        (const float*)d_in[6],
        (const float*)d_in[7],  (const float*)d_in[8],  (const float*)d_in[9],
        (const float*)d_in[10], (const float*)d_in[11], (const float*)d_in[12],
        (const float*)d_in[13], (const float*)d_in[14],
        /* ca_Wq/bq/Wk/bk (15-18) unused: one-hot cross-attn softmax */
        (const float*)d_in[19], (const float*)d_in[20], (const float*)d_in[21],
        (const float*)d_in[22],
        (const float*)d_in[23], (const float*)d_in[24], (const float*)d_in[25],
        (const float*)d_in[26],
        (const float*)d_in[27], (const float*)d_in[28],
        (float*)d_out);
    (void)in_sizes; (void)n_in; (void)out_size;
}